// round 1
// baseline (speedup 1.0000x reference)
#include <cuda_runtime.h>
#include <math.h>

#define NN 50000
#define D 128
#define D4 (D / 4)

// ---- device scratch (no allocations allowed) ----
__device__ float g_g[(size_t)NN * D];    // g = (A@W) * dinv[row]
__device__ float g_acc[(size_t)NN * D];  // accumulator (init = g, then += g[src])
__device__ float g_act[(size_t)NN * D];  // layer activation buffer
__device__ float g_dinv1[NN];
__device__ float g_dinv2[NN];

// ---------------------------------------------------------------------------
__global__ void zero_kernel(float* __restrict__ p, int n) {
    int i = blockIdx.x * blockDim.x + threadIdx.x;
    if (i < n) p[i] = 0.0f;
}

__global__ void deg_count_kernel(const int* __restrict__ dst, float* __restrict__ deg, int E) {
    int i = blockIdx.x * blockDim.x + threadIdx.x;
    if (i < E) atomicAdd(&deg[dst[i]], 1.0f);
}

__global__ void dinv_kernel(float* __restrict__ d, int n) {
    int i = blockIdx.x * blockDim.x + threadIdx.x;
    if (i < n) d[i] = rsqrtf(d[i] + 1.0f);  // +1 self loop; deg >= 1
}

// ---------------------------------------------------------------------------
// GEMM: g[row, col] = (sum_k A[row,k] * W[k,col]) * dinv[row]; acc = g.
// Tile: 64 rows x 128 cols per block, 256 threads, each thread 4x8 outputs.
// Smem: A tile (64x132 padded) + W chunk (16x128) = 42 KB (< 48 KB static).
__global__ __launch_bounds__(256) void gemm_scale_kernel(
    const float* __restrict__ A, const float* __restrict__ W,
    const float* __restrict__ dinv, float* __restrict__ g,
    float* __restrict__ acc, int nrows)
{
    __shared__ float As[64][132];   // pad 132: +4 banks/row, row base 16B aligned
    __shared__ float Ws[16][128];

    const int tid = threadIdx.x;
    const int row_base = blockIdx.x * 64;

    // Load A tile (zero-fill OOB rows)
    #pragma unroll
    for (int i = tid; i < 64 * 32; i += 256) {
        int r = i >> 5, c4 = i & 31;
        float4 v = make_float4(0.f, 0.f, 0.f, 0.f);
        if (row_base + r < nrows)
            v = reinterpret_cast<const float4*>(A)[(long)(row_base + r) * 32 + c4];
        *reinterpret_cast<float4*>(&As[r][c4 * 4]) = v;
    }

    const int tx = tid & 15;           // column group
    const int ty = tid >> 4;           // row group
    const int col0 = tx * 8;
    const int row0 = ty * 4;

    float accr[4][8];
    #pragma unroll
    for (int r = 0; r < 4; r++)
        #pragma unroll
        for (int c = 0; c < 8; c++) accr[r][c] = 0.0f;

    for (int kc = 0; kc < D; kc += 16) {
        __syncthreads();
        // Load W chunk: 16x128 floats = 512 float4, 2 per thread
        #pragma unroll
        for (int i = tid; i < 512; i += 256) {
            int kk = i >> 5, c4 = i & 31;
            reinterpret_cast<float4*>(&Ws[kk][c4 * 4])[0] =
                reinterpret_cast<const float4*>(W)[(kc + kk) * 32 + c4];
        }
        __syncthreads();

        #pragma unroll
        for (int kk = 0; kk < 16; kk++) {
            float a0 = As[row0 + 0][kc + kk];
            float a1 = As[row0 + 1][kc + kk];
            float a2 = As[row0 + 2][kc + kk];
            float a3 = As[row0 + 3][kc + kk];
            float4 w0 = *reinterpret_cast<const float4*>(&Ws[kk][col0]);
            float4 w1 = *reinterpret_cast<const float4*>(&Ws[kk][col0 + 4]);
            float wv[8] = {w0.x, w0.y, w0.z, w0.w, w1.x, w1.y, w1.z, w1.w};
            #pragma unroll
            for (int c = 0; c < 8; c++) {
                accr[0][c] = fmaf(a0, wv[c], accr[0][c]);
                accr[1][c] = fmaf(a1, wv[c], accr[1][c]);
                accr[2][c] = fmaf(a2, wv[c], accr[2][c]);
                accr[3][c] = fmaf(a3, wv[c], accr[3][c]);
            }
        }
    }

    // Epilogue: scale by dinv[row], write to g and acc (acc init = self-loop g)
    #pragma unroll
    for (int r = 0; r < 4; r++) {
        int row = row_base + row0 + r;
        if (row >= nrows) continue;
        float dv = dinv[row];
        float4 o0 = make_float4(accr[r][0] * dv, accr[r][1] * dv,
                                accr[r][2] * dv, accr[r][3] * dv);
        float4 o1 = make_float4(accr[r][4] * dv, accr[r][5] * dv,
                                accr[r][6] * dv, accr[r][7] * dv);
        long base = (long)row * 32 + (col0 >> 2);
        reinterpret_cast<float4*>(g)[base]     = o0;
        reinterpret_cast<float4*>(g)[base + 1] = o1;
        reinterpret_cast<float4*>(acc)[base]     = o0;
        reinterpret_cast<float4*>(acc)[base + 1] = o1;
    }
}

// ---------------------------------------------------------------------------
// Edge scatter: one warp per edge; acc[dst] += g[src] (128 floats = 32 x float4).
// Uses sm_90+ vectorized reduction red.global.add.v4.f32.
__global__ __launch_bounds__(256) void scatter_kernel(
    const int* __restrict__ ei, int E,
    const float4* __restrict__ g, float* __restrict__ acc)
{
    long idx = (long)blockIdx.x * blockDim.x + threadIdx.x;
    int e = (int)(idx >> 5);
    if (e >= E) return;
    int lane = (int)(idx & 31);
    int s = __ldg(&ei[e]);       // src (broadcast across warp)
    int d = __ldg(&ei[e + E]);   // dst
    float4 v = g[(long)s * 32 + lane];
    float* p = acc + ((long)d * 32 + lane) * 4;
    asm volatile("red.global.add.v4.f32 [%0], {%1, %2, %3, %4};"
                 :: "l"(p), "f"(v.x), "f"(v.y), "f"(v.z), "f"(v.w)
                 : "memory");
}

// ---------------------------------------------------------------------------
// out = act(dinv[row] * acc + b);  act: 0 = elu, 1 = relu.
__global__ __launch_bounds__(256) void finalize_kernel(
    const float4* __restrict__ acc, const float* __restrict__ dinv,
    const float4* __restrict__ b, float4* __restrict__ out1,
    float4* __restrict__ out2, int n, int relu_mode)
{
    int idx = blockIdx.x * blockDim.x + threadIdx.x;
    if (idx >= n * D4) return;
    int row = idx >> 5;     // D4 = 32 float4 per row
    int c4 = idx & 31;
    float dv = dinv[row];
    float4 v = acc[idx];
    float4 bb = b[c4];
    float o[4] = { fmaf(v.x, dv, bb.x), fmaf(v.y, dv, bb.y),
                   fmaf(v.z, dv, bb.z), fmaf(v.w, dv, bb.w) };
    if (relu_mode) {
        #pragma unroll
        for (int k = 0; k < 4; k++) o[k] = fmaxf(o[k], 0.0f);
    } else {
        #pragma unroll
        for (int k = 0; k < 4; k++) o[k] = (o[k] > 0.0f) ? o[k] : expm1f(o[k]);
    }
    float4 ov = make_float4(o[0], o[1], o[2], o[3]);
    out1[idx] = ov;
    if (out2) out2[idx] = ov;
}

// ---------------------------------------------------------------------------
extern "C" void kernel_launch(void* const* d_in, const int* in_sizes, int n_in,
                              void* d_out, int out_size)
{
    const float* x  = (const float*)d_in[0];
    const float* W1 = (const float*)d_in[1]; const float* b1 = (const float*)d_in[2];
    const float* W2 = (const float*)d_in[3]; const float* b2 = (const float*)d_in[4];
    const float* W3 = (const float*)d_in[5]; const float* b3 = (const float*)d_in[6];
    const float* W4 = (const float*)d_in[7]; const float* b4 = (const float*)d_in[8];
    const int* ei1 = (const int*)d_in[9];
    const int* ei2 = (const int*)d_in[10];
    const int E1 = in_sizes[9] / 2;
    const int E2 = in_sizes[10] / 2;

    float *gp, *accp, *actp, *dinv1, *dinv2;
    cudaGetSymbolAddress((void**)&gp,    g_g);
    cudaGetSymbolAddress((void**)&accp,  g_acc);
    cudaGetSymbolAddress((void**)&actp,  g_act);
    cudaGetSymbolAddress((void**)&dinv1, g_dinv1);
    cudaGetSymbolAddress((void**)&dinv2, g_dinv2);

    float* out_z = (float*)d_out;                    // z  = layer-2 output
    float* out_x = (float*)d_out + (long)NN * D;     // xr = layer-4 output

    const int nb_node = (NN + 255) / 256;

    // Degree / dinv for both edge sets (reused across layers)
    zero_kernel<<<nb_node, 256>>>(dinv1, NN);
    zero_kernel<<<nb_node, 256>>>(dinv2, NN);
    deg_count_kernel<<<(E1 + 255) / 256, 256>>>(ei1 + E1, dinv1, E1);
    deg_count_kernel<<<(E2 + 255) / 256, 256>>>(ei2 + E2, dinv2, E2);
    dinv_kernel<<<nb_node, 256>>>(dinv1, NN);
    dinv_kernel<<<nb_node, 256>>>(dinv2, NN);

    const int gemm_blocks = (NN + 63) / 64;
    const int fin_blocks  = (NN * D4 + 255) / 256;

    auto layer = [&](const float* A, const float* Wt, const float* bt,
                     const int* ei, int E, const float* dinv,
                     float* o1, float* o2, int relu) {
        gemm_scale_kernel<<<gemm_blocks, 256>>>(A, Wt, dinv, gp, accp, NN);
        long tot = (long)E * 32;
        scatter_kernel<<<(unsigned)((tot + 255) / 256), 256>>>(
            ei, E, (const float4*)gp, accp);
        finalize_kernel<<<fin_blocks, 256>>>(
            (const float4*)accp, dinv, (const float4*)bt,
            (float4*)o1, (float4*)o2, NN, relu);
    };

    layer(x,    W1, b1, ei1, E1, dinv1, actp, nullptr, 0);  // h  = elu(conv1)
    layer(actp, W2, b2, ei2, E2, dinv2, actp, out_z,  0);   // z  = elu(conv2)
    layer(actp, W3, b3, ei1, E1, dinv1, actp, nullptr, 0);  // h  = elu(conv3)
    layer(actp, W4, b4, ei2, E2, dinv2, out_x, nullptr, 1); // xr = relu(conv4)
}

// round 2
// speedup vs baseline: 1.2212x; 1.2212x over previous
#include <cuda_runtime.h>
#include <math.h>

#define NN 50000
#define D 128
#define D4 (D / 4)
#define EMAX 800000

// ---- device scratch (no allocations allowed) ----
__device__ float g_g[(size_t)NN * D];    // g = (A@W) * dinv[row]
__device__ float g_act[(size_t)NN * D];  // layer activation buffer
__device__ float g_dinv1[NN];
__device__ float g_dinv2[NN];
__device__ int   g_cnt1[NN];
__device__ int   g_cnt2[NN];
__device__ int   g_rowptr1[NN + 1];
__device__ int   g_rowptr2[NN + 1];
__device__ int   g_cursor1[NN];
__device__ int   g_cursor2[NN];
__device__ int   g_col1[EMAX];
__device__ int   g_col2[EMAX];

// ---------------------------------------------------------------------------
__global__ void zero_int_kernel(int* __restrict__ p, int n) {
    int i = blockIdx.x * blockDim.x + threadIdx.x;
    if (i < n) p[i] = 0;
}

__global__ void count_kernel(const int* __restrict__ dst, int* __restrict__ cnt, int E) {
    int i = blockIdx.x * blockDim.x + threadIdx.x;
    if (i < E) atomicAdd(&cnt[dst[i]], 1);
}

__global__ void dinv_kernel(const int* __restrict__ cnt, float* __restrict__ d, int n) {
    int i = blockIdx.x * blockDim.x + threadIdx.x;
    if (i < n) d[i] = rsqrtf((float)cnt[i] + 1.0f);  // +1 self loop
}

// Single-block exclusive scan over counts -> row_ptr (n+1) and cursor copy.
__global__ __launch_bounds__(1024) void scan_kernel(
    const int* __restrict__ cnt, int* __restrict__ row_ptr,
    int* __restrict__ cursor, int n)
{
    __shared__ int sh[1024];
    __shared__ int carry_sh;
    int tid = threadIdx.x;
    if (tid == 0) carry_sh = 0;
    __syncthreads();
    for (int base = 0; base < n; base += 1024) {
        int carry = carry_sh;
        int v = (base + tid < n) ? cnt[base + tid] : 0;
        sh[tid] = v;
        __syncthreads();
        #pragma unroll
        for (int off = 1; off < 1024; off <<= 1) {
            int t = (tid >= off) ? sh[tid - off] : 0;
            __syncthreads();
            sh[tid] += t;
            __syncthreads();
        }
        int incl = sh[tid];
        int excl = incl - v + carry;
        if (base + tid < n) { row_ptr[base + tid] = excl; cursor[base + tid] = excl; }
        int total = sh[1023];
        __syncthreads();
        if (tid == 0) carry_sh = carry + total;
        __syncthreads();
    }
    if (tid == 0) row_ptr[n] = carry_sh;
}

__global__ void fill_kernel(const int* __restrict__ ei, int E,
                            int* __restrict__ cursor, int* __restrict__ col)
{
    int e = blockIdx.x * blockDim.x + threadIdx.x;
    if (e >= E) return;
    int s = ei[e];
    int d = ei[e + E];
    int pos = atomicAdd(&cursor[d], 1);
    col[pos] = s;
}

// ---------------------------------------------------------------------------
// GEMM: g[row, col] = (sum_k A[row,k] * W[k,col]) * dinv[row].
// Tile: 64 rows x 128 cols per block, 256 threads, each thread 4x8 outputs.
__global__ __launch_bounds__(256) void gemm_scale_kernel(
    const float* __restrict__ A, const float* __restrict__ W,
    const float* __restrict__ dinv, float* __restrict__ g, int nrows)
{
    __shared__ float As[64][132];
    __shared__ float Ws[16][128];

    const int tid = threadIdx.x;
    const int row_base = blockIdx.x * 64;

    #pragma unroll
    for (int i = tid; i < 64 * 32; i += 256) {
        int r = i >> 5, c4 = i & 31;
        float4 v = make_float4(0.f, 0.f, 0.f, 0.f);
        if (row_base + r < nrows)
            v = reinterpret_cast<const float4*>(A)[(long)(row_base + r) * 32 + c4];
        *reinterpret_cast<float4*>(&As[r][c4 * 4]) = v;
    }

    const int tx = tid & 15;
    const int ty = tid >> 4;
    const int col0 = tx * 8;
    const int row0 = ty * 4;

    float accr[4][8];
    #pragma unroll
    for (int r = 0; r < 4; r++)
        #pragma unroll
        for (int c = 0; c < 8; c++) accr[r][c] = 0.0f;

    for (int kc = 0; kc < D; kc += 16) {
        __syncthreads();
        #pragma unroll
        for (int i = tid; i < 512; i += 256) {
            int kk = i >> 5, c4 = i & 31;
            reinterpret_cast<float4*>(&Ws[kk][c4 * 4])[0] =
                reinterpret_cast<const float4*>(W)[(kc + kk) * 32 + c4];
        }
        __syncthreads();

        #pragma unroll
        for (int kk = 0; kk < 16; kk++) {
            float a0 = As[row0 + 0][kc + kk];
            float a1 = As[row0 + 1][kc + kk];
            float a2 = As[row0 + 2][kc + kk];
            float a3 = As[row0 + 3][kc + kk];
            float4 w0 = *reinterpret_cast<const float4*>(&Ws[kk][col0]);
            float4 w1 = *reinterpret_cast<const float4*>(&Ws[kk][col0 + 4]);
            float wv[8] = {w0.x, w0.y, w0.z, w0.w, w1.x, w1.y, w1.z, w1.w};
            #pragma unroll
            for (int c = 0; c < 8; c++) {
                accr[0][c] = fmaf(a0, wv[c], accr[0][c]);
                accr[1][c] = fmaf(a1, wv[c], accr[1][c]);
                accr[2][c] = fmaf(a2, wv[c], accr[2][c]);
                accr[3][c] = fmaf(a3, wv[c], accr[3][c]);
            }
        }
    }

    #pragma unroll
    for (int r = 0; r < 4; r++) {
        int row = row_base + row0 + r;
        if (row >= nrows) continue;
        float dv = dinv[row];
        float4 o0 = make_float4(accr[r][0] * dv, accr[r][1] * dv,
                                accr[r][2] * dv, accr[r][3] * dv);
        float4 o1 = make_float4(accr[r][4] * dv, accr[r][5] * dv,
                                accr[r][6] * dv, accr[r][7] * dv);
        long base = (long)row * 32 + (col0 >> 2);
        reinterpret_cast<float4*>(g)[base]     = o0;
        reinterpret_cast<float4*>(g)[base + 1] = o1;
    }
}

// ---------------------------------------------------------------------------
// Gather + finalize: one warp per node.
// out[i] = act( dinv[i] * (g[i] + sum_{src in CSR[i]} g[src]) + b )
__global__ __launch_bounds__(256) void gather_finalize_kernel(
    const float4* __restrict__ g, const int* __restrict__ row_ptr,
    const int* __restrict__ col, const float* __restrict__ dinv,
    const float4* __restrict__ b, float4* __restrict__ out, int relu_mode)
{
    int warp = (blockIdx.x * blockDim.x + threadIdx.x) >> 5;
    int lane = threadIdx.x & 31;
    if (warp >= NN) return;

    long base = (long)warp * 32 + lane;
    float4 a = g[base];                       // self-loop term
    float4 a1 = make_float4(0.f, 0.f, 0.f, 0.f);

    int jb = __ldg(&row_ptr[warp]);
    int je = __ldg(&row_ptr[warp + 1]);
    int j = jb;
    for (; j + 1 < je; j += 2) {
        int s0 = __ldg(&col[j]);
        int s1 = __ldg(&col[j + 1]);
        float4 v0 = g[(long)s0 * 32 + lane];
        float4 v1 = g[(long)s1 * 32 + lane];
        a.x += v0.x; a.y += v0.y; a.z += v0.z; a.w += v0.w;
        a1.x += v1.x; a1.y += v1.y; a1.z += v1.z; a1.w += v1.w;
    }
    if (j < je) {
        int s = __ldg(&col[j]);
        float4 v = g[(long)s * 32 + lane];
        a.x += v.x; a.y += v.y; a.z += v.z; a.w += v.w;
    }
    a.x += a1.x; a.y += a1.y; a.z += a1.z; a.w += a1.w;

    float dv = dinv[warp];
    float4 bb = b[lane];
    float o[4] = { fmaf(a.x, dv, bb.x), fmaf(a.y, dv, bb.y),
                   fmaf(a.z, dv, bb.z), fmaf(a.w, dv, bb.w) };
    if (relu_mode) {
        #pragma unroll
        for (int k = 0; k < 4; k++) o[k] = fmaxf(o[k], 0.0f);
    } else {
        #pragma unroll
        for (int k = 0; k < 4; k++) o[k] = (o[k] > 0.0f) ? o[k] : expm1f(o[k]);
    }
    out[base] = make_float4(o[0], o[1], o[2], o[3]);
}

// ---------------------------------------------------------------------------
extern "C" void kernel_launch(void* const* d_in, const int* in_sizes, int n_in,
                              void* d_out, int out_size)
{
    const float* x  = (const float*)d_in[0];
    const float* W1 = (const float*)d_in[1]; const float* b1 = (const float*)d_in[2];
    const float* W2 = (const float*)d_in[3]; const float* b2 = (const float*)d_in[4];
    const float* W3 = (const float*)d_in[5]; const float* b3 = (const float*)d_in[6];
    const float* W4 = (const float*)d_in[7]; const float* b4 = (const float*)d_in[8];
    const int* ei1 = (const int*)d_in[9];
    const int* ei2 = (const int*)d_in[10];
    const int E1 = in_sizes[9] / 2;
    const int E2 = in_sizes[10] / 2;

    float *gp, *actp, *dinv1, *dinv2;
    int *cnt1, *cnt2, *rp1, *rp2, *cur1, *cur2, *col1, *col2;
    cudaGetSymbolAddress((void**)&gp,   g_g);
    cudaGetSymbolAddress((void**)&actp, g_act);
    cudaGetSymbolAddress((void**)&dinv1, g_dinv1);
    cudaGetSymbolAddress((void**)&dinv2, g_dinv2);
    cudaGetSymbolAddress((void**)&cnt1, g_cnt1);
    cudaGetSymbolAddress((void**)&cnt2, g_cnt2);
    cudaGetSymbolAddress((void**)&rp1,  g_rowptr1);
    cudaGetSymbolAddress((void**)&rp2,  g_rowptr2);
    cudaGetSymbolAddress((void**)&cur1, g_cursor1);
    cudaGetSymbolAddress((void**)&cur2, g_cursor2);
    cudaGetSymbolAddress((void**)&col1, g_col1);
    cudaGetSymbolAddress((void**)&col2, g_col2);

    float* out_z = (float*)d_out;                  // z  = layer-2 output
    float* out_x = (float*)d_out + (long)NN * D;   // xr = layer-4 output

    const int nb_node = (NN + 255) / 256;

    // ---- CSR build for both edge sets ----
    zero_int_kernel<<<nb_node, 256>>>(cnt1, NN);
    zero_int_kernel<<<nb_node, 256>>>(cnt2, NN);
    count_kernel<<<(E1 + 255) / 256, 256>>>(ei1 + E1, cnt1, E1);
    count_kernel<<<(E2 + 255) / 256, 256>>>(ei2 + E2, cnt2, E2);
    dinv_kernel<<<nb_node, 256>>>(cnt1, dinv1, NN);
    dinv_kernel<<<nb_node, 256>>>(cnt2, dinv2, NN);
    scan_kernel<<<1, 1024>>>(cnt1, rp1, cur1, NN);
    scan_kernel<<<1, 1024>>>(cnt2, rp2, cur2, NN);
    fill_kernel<<<(E1 + 255) / 256, 256>>>(ei1, E1, cur1, col1);
    fill_kernel<<<(E2 + 255) / 256, 256>>>(ei2, E2, cur2, col2);

    const int gemm_blocks = (NN + 63) / 64;
    const int gat_blocks  = (NN * 32 + 255) / 256;

    auto layer = [&](const float* A, const float* Wt, const float* bt,
                     const int* rp, const int* col, const float* dinv,
                     float* o, int relu) {
        gemm_scale_kernel<<<gemm_blocks, 256>>>(A, Wt, dinv, gp, NN);
        gather_finalize_kernel<<<gat_blocks, 256>>>(
            (const float4*)gp, rp, col, dinv, (const float4*)bt,
            (float4*)o, relu);
    };

    layer(x,     W1, b1, rp1, col1, dinv1, actp,  0);  // h  = elu(conv1)
    layer(actp,  W2, b2, rp2, col2, dinv2, out_z, 0);  // z  = elu(conv2)
    layer(out_z, W3, b3, rp1, col1, dinv1, actp,  0);  // h  = elu(conv3)
    layer(actp,  W4, b4, rp2, col2, dinv2, out_x, 1);  // xr = relu(conv4)
}

// round 3
// speedup vs baseline: 1.3551x; 1.1097x over previous
#include <cuda_runtime.h>
#include <math.h>

#define NN 50000
#define D 128
#define D4 (D / 4)
#define EMAX 800000

// ---- device scratch (no allocations allowed) ----
__device__ float g_g[(size_t)NN * D];    // g = (A@W) * dinv[row]
__device__ float g_act[(size_t)NN * D];  // layer activation buffer
__device__ float g_dinv1[NN];
__device__ float g_dinv2[NN];
__device__ int   g_cnt1[NN];
__device__ int   g_cnt2[NN];
__device__ int   g_rowptr1[NN + 1];
__device__ int   g_rowptr2[NN + 1];
__device__ int   g_cursor1[NN];
__device__ int   g_cursor2[NN];
__device__ int   g_col1[EMAX];
__device__ int   g_col2[EMAX];

// ---- packed f32x2 helpers (sm_103a) ----
__device__ __forceinline__ unsigned long long pack2(float a) {
    unsigned long long r;
    asm("mov.b64 %0, {%1, %1};" : "=l"(r) : "f"(a));
    return r;
}
__device__ __forceinline__ void fma2(unsigned long long& d,
                                     unsigned long long a, unsigned long long b) {
    asm("fma.rn.f32x2 %0, %1, %2, %0;" : "+l"(d) : "l"(a), "l"(b));
}
__device__ __forceinline__ unsigned long long mul2(unsigned long long a,
                                                   unsigned long long b) {
    unsigned long long d;
    asm("mul.rn.f32x2 %0, %1, %2;" : "=l"(d) : "l"(a), "l"(b));
    return d;
}

// ---------------------------------------------------------------------------
__global__ void zero_int_kernel(int* __restrict__ p, int n) {
    int i = blockIdx.x * blockDim.x + threadIdx.x;
    if (i < n) p[i] = 0;
}

__global__ void count_kernel(const int* __restrict__ dst, int* __restrict__ cnt, int E) {
    int i = blockIdx.x * blockDim.x + threadIdx.x;
    if (i < E) atomicAdd(&cnt[dst[i]], 1);
}

__global__ void dinv_kernel(const int* __restrict__ cnt, float* __restrict__ d, int n) {
    int i = blockIdx.x * blockDim.x + threadIdx.x;
    if (i < n) d[i] = rsqrtf((float)cnt[i] + 1.0f);  // +1 self loop
}

// Single-block exclusive scan (warp-shuffle based; 2 barriers per 1024-tile).
__global__ __launch_bounds__(1024) void scan_kernel(
    const int* __restrict__ cnt, int* __restrict__ row_ptr,
    int* __restrict__ cursor, int n)
{
    __shared__ int warp_sums[32];
    __shared__ int carry_sh;
    const int tid = threadIdx.x;
    const int lane = tid & 31;
    const int wid = tid >> 5;
    if (tid == 0) carry_sh = 0;
    __syncthreads();

    for (int base = 0; base < n; base += 1024) {
        int v = (base + tid < n) ? cnt[base + tid] : 0;
        int incl = v;
        #pragma unroll
        for (int off = 1; off < 32; off <<= 1) {
            int t = __shfl_up_sync(0xFFFFFFFFu, incl, off);
            if (lane >= off) incl += t;
        }
        if (lane == 31) warp_sums[wid] = incl;
        __syncthreads();
        if (wid == 0) {
            int s = warp_sums[lane];
            #pragma unroll
            for (int off = 1; off < 32; off <<= 1) {
                int t = __shfl_up_sync(0xFFFFFFFFu, s, off);
                if (lane >= off) s += t;
            }
            warp_sums[lane] = s;
        }
        __syncthreads();
        int carry = carry_sh;
        int woff = (wid > 0) ? warp_sums[wid - 1] : 0;
        int excl = incl - v + woff + carry;
        if (base + tid < n) { row_ptr[base + tid] = excl; cursor[base + tid] = excl; }
        int total = warp_sums[31];
        __syncthreads();
        if (tid == 0) carry_sh = carry + total;
        __syncthreads();
    }
    if (tid == 0) row_ptr[n] = carry_sh;
}

__global__ void fill_kernel(const int* __restrict__ ei, int E,
                            int* __restrict__ cursor, int* __restrict__ col)
{
    int e = blockIdx.x * blockDim.x + threadIdx.x;
    if (e >= E) return;
    int s = ei[e];
    int d = ei[e + E];
    int pos = atomicAdd(&cursor[d], 1);
    col[pos] = s;
}

// ---------------------------------------------------------------------------
// GEMM: g[row, col] = (sum_k A[row,k] * W[k,col]) * dinv[row].
// 64x128 tile, 256 threads, 4x8 outputs per thread, packed fma.rn.f32x2 math.
__global__ __launch_bounds__(256) void gemm_scale_kernel(
    const float* __restrict__ A, const float* __restrict__ W,
    const float* __restrict__ dinv, float* __restrict__ g, int nrows)
{
    __shared__ float As[64][132];
    __shared__ float Ws[16][128];

    const int tid = threadIdx.x;
    const int row_base = blockIdx.x * 64;

    #pragma unroll
    for (int i = tid; i < 64 * 32; i += 256) {
        int r = i >> 5, c4 = i & 31;
        float4 v = make_float4(0.f, 0.f, 0.f, 0.f);
        if (row_base + r < nrows)
            v = reinterpret_cast<const float4*>(A)[(long)(row_base + r) * 32 + c4];
        *reinterpret_cast<float4*>(&As[r][c4 * 4]) = v;
    }

    const int tx = tid & 15;
    const int ty = tid >> 4;
    const int col0 = tx * 8;       // 8 output cols = 4 f32x2 pairs
    const int row0 = ty * 4;

    unsigned long long acc2[4][4];
    #pragma unroll
    for (int r = 0; r < 4; r++)
        #pragma unroll
        for (int c = 0; c < 4; c++) acc2[r][c] = 0ull;

    for (int kc = 0; kc < D; kc += 16) {
        __syncthreads();
        #pragma unroll
        for (int i = tid; i < 512; i += 256) {
            int kk = i >> 5, c4 = i & 31;
            reinterpret_cast<float4*>(&Ws[kk][c4 * 4])[0] =
                reinterpret_cast<const float4*>(W)[(kc + kk) * 32 + c4];
        }
        __syncthreads();

        #pragma unroll
        for (int kk4 = 0; kk4 < 16; kk4 += 4) {
            // A fragments: 4 rows x 4 consecutive k as float4
            float4 av[4];
            #pragma unroll
            for (int r = 0; r < 4; r++)
                av[r] = *reinterpret_cast<const float4*>(&As[row0 + r][kc + kk4]);

            #pragma unroll
            for (int j = 0; j < 4; j++) {
                union { float4 f; unsigned long long u[2]; } w0, w1;
                w0.f = *reinterpret_cast<const float4*>(&Ws[kk4 + j][col0]);
                w1.f = *reinterpret_cast<const float4*>(&Ws[kk4 + j][col0 + 4]);
                unsigned long long wv[4] = { w0.u[0], w0.u[1], w1.u[0], w1.u[1] };
                const float* avf = reinterpret_cast<const float*>(av);
                #pragma unroll
                for (int r = 0; r < 4; r++) {
                    unsigned long long aa = pack2(avf[r * 4 + j]);
                    fma2(acc2[r][0], aa, wv[0]);
                    fma2(acc2[r][1], aa, wv[1]);
                    fma2(acc2[r][2], aa, wv[2]);
                    fma2(acc2[r][3], aa, wv[3]);
                }
            }
        }
    }

    #pragma unroll
    for (int r = 0; r < 4; r++) {
        int row = row_base + row0 + r;
        if (row >= nrows) continue;
        unsigned long long dd = pack2(dinv[row]);
        union { float4 f; unsigned long long u[2]; } o0, o1;
        o0.u[0] = mul2(acc2[r][0], dd);
        o0.u[1] = mul2(acc2[r][1], dd);
        o1.u[0] = mul2(acc2[r][2], dd);
        o1.u[1] = mul2(acc2[r][3], dd);
        long base = (long)row * 32 + (col0 >> 2);
        reinterpret_cast<float4*>(g)[base]     = o0.f;
        reinterpret_cast<float4*>(g)[base + 1] = o1.f;
    }
}

// ---------------------------------------------------------------------------
// Gather + finalize: one warp per node.
// out[i] = act( dinv[i] * (g[i] + sum_{src in CSR[i]} g[src]) + b )
__global__ __launch_bounds__(256) void gather_finalize_kernel(
    const float4* __restrict__ g, const int* __restrict__ row_ptr,
    const int* __restrict__ col, const float* __restrict__ dinv,
    const float4* __restrict__ b, float4* __restrict__ out, int relu_mode)
{
    int warp = (blockIdx.x * blockDim.x + threadIdx.x) >> 5;
    int lane = threadIdx.x & 31;
    if (warp >= NN) return;

    long base = (long)warp * 32 + lane;
    float4 a = g[base];                       // self-loop term
    float4 a1 = make_float4(0.f, 0.f, 0.f, 0.f);

    int jb = __ldg(&row_ptr[warp]);
    int je = __ldg(&row_ptr[warp + 1]);
    int j = jb;
    for (; j + 1 < je; j += 2) {
        int s0 = __ldg(&col[j]);
        int s1 = __ldg(&col[j + 1]);
        float4 v0 = g[(long)s0 * 32 + lane];
        float4 v1 = g[(long)s1 * 32 + lane];
        a.x += v0.x; a.y += v0.y; a.z += v0.z; a.w += v0.w;
        a1.x += v1.x; a1.y += v1.y; a1.z += v1.z; a1.w += v1.w;
    }
    if (j < je) {
        int s = __ldg(&col[j]);
        float4 v = g[(long)s * 32 + lane];
        a.x += v.x; a.y += v.y; a.z += v.z; a.w += v.w;
    }
    a.x += a1.x; a.y += a1.y; a.z += a1.z; a.w += a1.w;

    float dv = dinv[warp];
    float4 bb = b[lane];
    float o[4] = { fmaf(a.x, dv, bb.x), fmaf(a.y, dv, bb.y),
                   fmaf(a.z, dv, bb.z), fmaf(a.w, dv, bb.w) };
    if (relu_mode) {
        #pragma unroll
        for (int k = 0; k < 4; k++) o[k] = fmaxf(o[k], 0.0f);
    } else {
        #pragma unroll
        for (int k = 0; k < 4; k++) o[k] = (o[k] > 0.0f) ? o[k] : expm1f(o[k]);
    }
    out[base] = make_float4(o[0], o[1], o[2], o[3]);
}

// ---------------------------------------------------------------------------
extern "C" void kernel_launch(void* const* d_in, const int* in_sizes, int n_in,
                              void* d_out, int out_size)
{
    const float* x  = (const float*)d_in[0];
    const float* W1 = (const float*)d_in[1]; const float* b1 = (const float*)d_in[2];
    const float* W2 = (const float*)d_in[3]; const float* b2 = (const float*)d_in[4];
    const float* W3 = (const float*)d_in[5]; const float* b3 = (const float*)d_in[6];
    const float* W4 = (const float*)d_in[7]; const float* b4 = (const float*)d_in[8];
    const int* ei1 = (const int*)d_in[9];
    const int* ei2 = (const int*)d_in[10];
    const int E1 = in_sizes[9] / 2;
    const int E2 = in_sizes[10] / 2;

    float *gp, *actp, *dinv1, *dinv2;
    int *cnt1, *cnt2, *rp1, *rp2, *cur1, *cur2, *col1, *col2;
    cudaGetSymbolAddress((void**)&gp,   g_g);
    cudaGetSymbolAddress((void**)&actp, g_act);
    cudaGetSymbolAddress((void**)&dinv1, g_dinv1);
    cudaGetSymbolAddress((void**)&dinv2, g_dinv2);
    cudaGetSymbolAddress((void**)&cnt1, g_cnt1);
    cudaGetSymbolAddress((void**)&cnt2, g_cnt2);
    cudaGetSymbolAddress((void**)&rp1,  g_rowptr1);
    cudaGetSymbolAddress((void**)&rp2,  g_rowptr2);
    cudaGetSymbolAddress((void**)&cur1, g_cursor1);
    cudaGetSymbolAddress((void**)&cur2, g_cursor2);
    cudaGetSymbolAddress((void**)&col1, g_col1);
    cudaGetSymbolAddress((void**)&col2, g_col2);

    float* out_z = (float*)d_out;                  // z  = layer-2 output
    float* out_x = (float*)d_out + (long)NN * D;   // xr = layer-4 output

    const int nb_node = (NN + 255) / 256;

    // ---- CSR build for both edge sets ----
    zero_int_kernel<<<nb_node, 256>>>(cnt1, NN);
    zero_int_kernel<<<nb_node, 256>>>(cnt2, NN);
    count_kernel<<<(E1 + 255) / 256, 256>>>(ei1 + E1, cnt1, E1);
    count_kernel<<<(E2 + 255) / 256, 256>>>(ei2 + E2, cnt2, E2);
    dinv_kernel<<<nb_node, 256>>>(cnt1, dinv1, NN);
    dinv_kernel<<<nb_node, 256>>>(cnt2, dinv2, NN);
    scan_kernel<<<1, 1024>>>(cnt1, rp1, cur1, NN);
    scan_kernel<<<1, 1024>>>(cnt2, rp2, cur2, NN);
    fill_kernel<<<(E1 + 255) / 256, 256>>>(ei1, E1, cur1, col1);
    fill_kernel<<<(E2 + 255) / 256, 256>>>(ei2, E2, cur2, col2);

    const int gemm_blocks = (NN + 63) / 64;
    const int gat_blocks  = (NN * 32 + 255) / 256;

    auto layer = [&](const float* A, const float* Wt, const float* bt,
                     const int* rp, const int* col, const float* dinv,
                     float* o, int relu) {
        gemm_scale_kernel<<<gemm_blocks, 256>>>(A, Wt, dinv, gp, NN);
        gather_finalize_kernel<<<gat_blocks, 256>>>(
            (const float4*)gp, rp, col, dinv, (const float4*)bt,
            (float4*)o, relu);
    };

    layer(x,     W1, b1, rp1, col1, dinv1, actp,  0);  // h  = elu(conv1)
    layer(actp,  W2, b2, rp2, col2, dinv2, out_z, 0);  // z  = elu(conv2)
    layer(out_z, W3, b3, rp1, col1, dinv1, actp,  0);  // h  = elu(conv3)
    layer(actp,  W4, b4, rp2, col2, dinv2, out_x, 1);  // xr = relu(conv4)
}

// round 4
// speedup vs baseline: 1.7327x; 1.2786x over previous
#include <cuda_runtime.h>
#include <math.h>

#define NN 50000
#define D 128
#define EMAX 800000

// ---- device scratch (no allocations allowed) ----
__device__ float g_g[(size_t)NN * D];
__device__ float g_act[(size_t)NN * D];
__device__ float g_dinv1[NN];
__device__ float g_dinv2[NN];
__device__ int   g_cnt1[NN];
__device__ int   g_cnt2[NN];
__device__ int   g_rowptr1[NN + 1];
__device__ int   g_rowptr2[NN + 1];
__device__ int   g_cursor1[NN];
__device__ int   g_cursor2[NN];
__device__ int   g_col1[EMAX];
__device__ int   g_col2[EMAX];

// ---- packed f32x2 helpers (sm_103a) ----
__device__ __forceinline__ unsigned long long pack2(float a) {
    unsigned long long r;
    asm("mov.b64 %0, {%1, %1};" : "=l"(r) : "f"(a));
    return r;
}
__device__ __forceinline__ void fma2(unsigned long long& d,
                                     unsigned long long a, unsigned long long b) {
    asm("fma.rn.f32x2 %0, %1, %2, %0;" : "+l"(d) : "l"(a), "l"(b));
}
__device__ __forceinline__ unsigned long long mul2(unsigned long long a,
                                                   unsigned long long b) {
    unsigned long long d;
    asm("mul.rn.f32x2 %0, %1, %2;" : "=l"(d) : "l"(a), "l"(b));
    return d;
}

// ---------------------------------------------------------------------------
// Fused CSR-build helpers (each launch handles BOTH edge sets).
__global__ void zero_both_kernel(int* __restrict__ c1, int* __restrict__ c2) {
    int i = blockIdx.x * blockDim.x + threadIdx.x;
    if (i < NN) c1[i] = 0;
    else if (i < 2 * NN) c2[i - NN] = 0;
}

__global__ void count_both_kernel(const int* __restrict__ ei1, int E1,
                                  const int* __restrict__ ei2, int E2,
                                  int* __restrict__ c1, int* __restrict__ c2) {
    int i = blockIdx.x * blockDim.x + threadIdx.x;
    if (i < E1) atomicAdd(&c1[ei1[E1 + i]], 1);
    else if (i < E1 + E2) atomicAdd(&c2[ei2[E2 + (i - E1)]], 1);
}

__global__ void dinv_both_kernel(const int* __restrict__ c1, float* __restrict__ d1,
                                 const int* __restrict__ c2, float* __restrict__ d2) {
    int i = blockIdx.x * blockDim.x + threadIdx.x;
    if (i < NN) d1[i] = rsqrtf((float)c1[i] + 1.0f);
    else if (i < 2 * NN) d2[i - NN] = rsqrtf((float)c2[i - NN] + 1.0f);
}

// Exclusive scan; 2 independent blocks (one per edge set), warp-shuffle based.
__global__ __launch_bounds__(1024) void scan_kernel(
    const int* __restrict__ cntA, int* __restrict__ rpA, int* __restrict__ curA,
    const int* __restrict__ cntB, int* __restrict__ rpB, int* __restrict__ curB,
    int n)
{
    const int* cnt = (blockIdx.x == 0) ? cntA : cntB;
    int* row_ptr   = (blockIdx.x == 0) ? rpA  : rpB;
    int* cursor    = (blockIdx.x == 0) ? curA : curB;

    __shared__ int warp_sums[32];
    __shared__ int carry_sh;
    const int tid = threadIdx.x;
    const int lane = tid & 31;
    const int wid = tid >> 5;
    if (tid == 0) carry_sh = 0;
    __syncthreads();

    for (int base = 0; base < n; base += 1024) {
        int v = (base + tid < n) ? cnt[base + tid] : 0;
        int incl = v;
        #pragma unroll
        for (int off = 1; off < 32; off <<= 1) {
            int t = __shfl_up_sync(0xFFFFFFFFu, incl, off);
            if (lane >= off) incl += t;
        }
        if (lane == 31) warp_sums[wid] = incl;
        __syncthreads();
        if (wid == 0) {
            int s = warp_sums[lane];
            #pragma unroll
            for (int off = 1; off < 32; off <<= 1) {
                int t = __shfl_up_sync(0xFFFFFFFFu, s, off);
                if (lane >= off) s += t;
            }
            warp_sums[lane] = s;
        }
        __syncthreads();
        int carry = carry_sh;
        int woff = (wid > 0) ? warp_sums[wid - 1] : 0;
        int excl = incl - v + woff + carry;
        if (base + tid < n) { row_ptr[base + tid] = excl; cursor[base + tid] = excl; }
        int total = warp_sums[31];
        __syncthreads();
        if (tid == 0) carry_sh = carry + total;
        __syncthreads();
    }
    if (tid == 0) row_ptr[n] = carry_sh;
}

__global__ void fill_both_kernel(const int* __restrict__ ei1, int E1,
                                 int* __restrict__ cur1, int* __restrict__ col1,
                                 const int* __restrict__ ei2, int E2,
                                 int* __restrict__ cur2, int* __restrict__ col2)
{
    int i = blockIdx.x * blockDim.x + threadIdx.x;
    if (i < E1) {
        int s = ei1[i], d = ei1[E1 + i];
        col1[atomicAdd(&cur1[d], 1)] = s;
    } else if (i < E1 + E2) {
        int e = i - E1;
        int s = ei2[e], d = ei2[E2 + e];
        col2[atomicAdd(&cur2[d], 1)] = s;
    }
}

// ---------------------------------------------------------------------------
// GEMM: g[row, col] = (sum_k A[row,k] * W[k,col]) * dinv[row].
// 64x128 block tile, 128 threads, 8x8 outputs per thread (f32x2 packed).
__global__ __launch_bounds__(128) void gemm_scale_kernel(
    const float* __restrict__ A, const float* __restrict__ W,
    const float* __restrict__ dinv, float* __restrict__ g, int nrows)
{
    __shared__ float As[64][132];
    __shared__ float Ws[16][128];

    const int tid = threadIdx.x;
    const int row_base = blockIdx.x * 64;

    #pragma unroll
    for (int i = tid; i < 64 * 32; i += 128) {
        int r = i >> 5, c4 = i & 31;
        float4 v = make_float4(0.f, 0.f, 0.f, 0.f);
        if (row_base + r < nrows)
            v = reinterpret_cast<const float4*>(A)[(long)(row_base + r) * 32 + c4];
        *reinterpret_cast<float4*>(&As[r][c4 * 4]) = v;
    }

    const int tx = tid & 15;       // 16 col groups of 8
    const int ty = tid >> 4;       // 8 row groups of 8
    const int col0 = tx * 8;
    const int row0 = ty * 8;

    unsigned long long acc2[8][4];
    #pragma unroll
    for (int r = 0; r < 8; r++)
        #pragma unroll
        for (int c = 0; c < 4; c++) acc2[r][c] = 0ull;

    for (int kc = 0; kc < D; kc += 16) {
        __syncthreads();
        #pragma unroll
        for (int i = tid; i < 512; i += 128) {
            int kk = i >> 5, c4 = i & 31;
            reinterpret_cast<float4*>(&Ws[kk][c4 * 4])[0] =
                reinterpret_cast<const float4*>(W)[(kc + kk) * 32 + c4];
        }
        __syncthreads();

        #pragma unroll
        for (int kk4 = 0; kk4 < 16; kk4 += 4) {
            float4 av[8];
            #pragma unroll
            for (int r = 0; r < 8; r++)
                av[r] = *reinterpret_cast<const float4*>(&As[row0 + r][kc + kk4]);

            #pragma unroll
            for (int j = 0; j < 4; j++) {
                union { float4 f; unsigned long long u[2]; } w0, w1;
                w0.f = *reinterpret_cast<const float4*>(&Ws[kk4 + j][col0]);
                w1.f = *reinterpret_cast<const float4*>(&Ws[kk4 + j][col0 + 4]);
                unsigned long long wv[4] = { w0.u[0], w0.u[1], w1.u[0], w1.u[1] };
                const float* avf = reinterpret_cast<const float*>(av);
                #pragma unroll
                for (int r = 0; r < 8; r++) {
                    unsigned long long aa = pack2(avf[r * 4 + j]);
                    fma2(acc2[r][0], aa, wv[0]);
                    fma2(acc2[r][1], aa, wv[1]);
                    fma2(acc2[r][2], aa, wv[2]);
                    fma2(acc2[r][3], aa, wv[3]);
                }
            }
        }
    }

    #pragma unroll
    for (int r = 0; r < 8; r++) {
        int row = row_base + row0 + r;
        if (row >= nrows) continue;
        unsigned long long dd = pack2(dinv[row]);
        union { float4 f; unsigned long long u[2]; } o0, o1;
        o0.u[0] = mul2(acc2[r][0], dd);
        o0.u[1] = mul2(acc2[r][1], dd);
        o1.u[0] = mul2(acc2[r][2], dd);
        o1.u[1] = mul2(acc2[r][3], dd);
        long base = (long)row * 32 + (col0 >> 2);
        reinterpret_cast<float4*>(g)[base]     = o0.f;
        reinterpret_cast<float4*>(g)[base + 1] = o1.f;
    }
}

// ---------------------------------------------------------------------------
// Gather + finalize: one warp per node, 4-way unrolled for MLP.
__global__ __launch_bounds__(256) void gather_finalize_kernel(
    const float4* __restrict__ g, const int* __restrict__ row_ptr,
    const int* __restrict__ col, const float* __restrict__ dinv,
    const float4* __restrict__ b, float4* __restrict__ out, int relu_mode)
{
    int warp = (blockIdx.x * blockDim.x + threadIdx.x) >> 5;
    int lane = threadIdx.x & 31;
    if (warp >= NN) return;

    long base = (long)warp * 32 + lane;
    float4 a0 = g[base];                        // self-loop term
    float4 a1 = make_float4(0.f, 0.f, 0.f, 0.f);
    float4 a2 = make_float4(0.f, 0.f, 0.f, 0.f);
    float4 a3 = make_float4(0.f, 0.f, 0.f, 0.f);

    int jb = __ldg(&row_ptr[warp]);
    int je = __ldg(&row_ptr[warp + 1]);
    int j = jb;
    for (; j + 3 < je; j += 4) {
        int s0 = __ldg(&col[j]);
        int s1 = __ldg(&col[j + 1]);
        int s2 = __ldg(&col[j + 2]);
        int s3 = __ldg(&col[j + 3]);
        float4 v0 = g[(long)s0 * 32 + lane];
        float4 v1 = g[(long)s1 * 32 + lane];
        float4 v2 = g[(long)s2 * 32 + lane];
        float4 v3 = g[(long)s3 * 32 + lane];
        a0.x += v0.x; a0.y += v0.y; a0.z += v0.z; a0.w += v0.w;
        a1.x += v1.x; a1.y += v1.y; a1.z += v1.z; a1.w += v1.w;
        a2.x += v2.x; a2.y += v2.y; a2.z += v2.z; a2.w += v2.w;
        a3.x += v3.x; a3.y += v3.y; a3.z += v3.z; a3.w += v3.w;
    }
    for (; j < je; j++) {
        int s = __ldg(&col[j]);
        float4 v = g[(long)s * 32 + lane];
        a0.x += v.x; a0.y += v.y; a0.z += v.z; a0.w += v.w;
    }
    a0.x += a1.x + a2.x + a3.x;
    a0.y += a1.y + a2.y + a3.y;
    a0.z += a1.z + a2.z + a3.z;
    a0.w += a1.w + a2.w + a3.w;

    float dv = dinv[warp];
    float4 bb = b[lane];
    float o[4] = { fmaf(a0.x, dv, bb.x), fmaf(a0.y, dv, bb.y),
                   fmaf(a0.z, dv, bb.z), fmaf(a0.w, dv, bb.w) };
    if (relu_mode) {
        #pragma unroll
        for (int k = 0; k < 4; k++) o[k] = fmaxf(o[k], 0.0f);
    } else {
        #pragma unroll
        for (int k = 0; k < 4; k++) o[k] = (o[k] > 0.0f) ? o[k] : expm1f(o[k]);
    }
    out[base] = make_float4(o[0], o[1], o[2], o[3]);
}

// ---------------------------------------------------------------------------
extern "C" void kernel_launch(void* const* d_in, const int* in_sizes, int n_in,
                              void* d_out, int out_size)
{
    const float* x  = (const float*)d_in[0];
    const float* W1 = (const float*)d_in[1]; const float* b1 = (const float*)d_in[2];
    const float* W2 = (const float*)d_in[3]; const float* b2 = (const float*)d_in[4];
    const float* W3 = (const float*)d_in[5]; const float* b3 = (const float*)d_in[6];
    const float* W4 = (const float*)d_in[7]; const float* b4 = (const float*)d_in[8];
    const int* ei1 = (const int*)d_in[9];
    const int* ei2 = (const int*)d_in[10];
    const int E1 = in_sizes[9] / 2;
    const int E2 = in_sizes[10] / 2;

    float *gp, *actp, *dinv1, *dinv2;
    int *cnt1, *cnt2, *rp1, *rp2, *cur1, *cur2, *col1, *col2;
    cudaGetSymbolAddress((void**)&gp,   g_g);
    cudaGetSymbolAddress((void**)&actp, g_act);
    cudaGetSymbolAddress((void**)&dinv1, g_dinv1);
    cudaGetSymbolAddress((void**)&dinv2, g_dinv2);
    cudaGetSymbolAddress((void**)&cnt1, g_cnt1);
    cudaGetSymbolAddress((void**)&cnt2, g_cnt2);
    cudaGetSymbolAddress((void**)&rp1,  g_rowptr1);
    cudaGetSymbolAddress((void**)&rp2,  g_rowptr2);
    cudaGetSymbolAddress((void**)&cur1, g_cursor1);
    cudaGetSymbolAddress((void**)&cur2, g_cursor2);
    cudaGetSymbolAddress((void**)&col1, g_col1);
    cudaGetSymbolAddress((void**)&col2, g_col2);

    float* out_z = (float*)d_out;
    float* out_x = (float*)d_out + (long)NN * D;

    // ---- CSR build (both edge sets per launch) ----
    zero_both_kernel<<<(2 * NN + 255) / 256, 256>>>(cnt1, cnt2);
    count_both_kernel<<<(E1 + E2 + 255) / 256, 256>>>(ei1, E1, ei2, E2, cnt1, cnt2);
    dinv_both_kernel<<<(2 * NN + 255) / 256, 256>>>(cnt1, dinv1, cnt2, dinv2);
    scan_kernel<<<2, 1024>>>(cnt1, rp1, cur1, cnt2, rp2, cur2, NN);
    fill_both_kernel<<<(E1 + E2 + 255) / 256, 256>>>(ei1, E1, cur1, col1,
                                                     ei2, E2, cur2, col2);

    const int gemm_blocks = (NN + 63) / 64;
    const int gat_blocks  = (NN * 32 + 255) / 256;

    auto layer = [&](const float* A, const float* Wt, const float* bt,
                     const int* rp, const int* col, const float* dinv,
                     float* o, int relu) {
        gemm_scale_kernel<<<gemm_blocks, 128>>>(A, Wt, dinv, gp, NN);
        gather_finalize_kernel<<<gat_blocks, 256>>>(
            (const float4*)gp, rp, col, dinv, (const float4*)bt,
            (float4*)o, relu);
    };

    layer(x,     W1, b1, rp1, col1, dinv1, actp,  0);  // h  = elu(conv1)
    layer(actp,  W2, b2, rp2, col2, dinv2, out_z, 0);  // z  = elu(conv2)
    layer(out_z, W3, b3, rp1, col1, dinv1, actp,  0);  // h  = elu(conv3)
    layer(actp,  W4, b4, rp2, col2, dinv2, out_x, 1);  // xr = relu(conv4)
}

// round 5
// speedup vs baseline: 1.8752x; 1.0822x over previous
#include <cuda_runtime.h>
#include <math.h>

#define NN 50000
#define D 128
#define EMAX 800000
#define TILE 1024
#define NPART ((NN + TILE - 1) / TILE)   // 49

// ---- device scratch (no allocations allowed) ----
__device__ float g_g[(size_t)NN * D];
__device__ float g_act[(size_t)NN * D];
__device__ float g_dinv1[NN];
__device__ float g_dinv2[NN];
__device__ int   g_cnt1[NN];
__device__ int   g_cnt2[NN];
__device__ int   g_rowptr1[NN + 1];
__device__ int   g_rowptr2[NN + 1];
__device__ int   g_cursor1[NN];
__device__ int   g_cursor2[NN];
__device__ int   g_col1[EMAX];
__device__ int   g_col2[EMAX];
__device__ int   g_part1[NPART];
__device__ int   g_part2[NPART];

// ---- packed f32x2 helpers (sm_103a) ----
__device__ __forceinline__ unsigned long long pack2(float a) {
    unsigned long long r;
    asm("mov.b64 %0, {%1, %1};" : "=l"(r) : "f"(a));
    return r;
}
__device__ __forceinline__ void fma2(unsigned long long& d,
                                     unsigned long long a, unsigned long long b) {
    asm("fma.rn.f32x2 %0, %1, %2, %0;" : "+l"(d) : "l"(a), "l"(b));
}
__device__ __forceinline__ unsigned long long mul2(unsigned long long a,
                                                   unsigned long long b) {
    unsigned long long d;
    asm("mul.rn.f32x2 %0, %1, %2;" : "=l"(d) : "l"(a), "l"(b));
    return d;
}

// ---------------------------------------------------------------------------
__global__ void zero_both_kernel(int* __restrict__ c1, int* __restrict__ c2) {
    int i = blockIdx.x * blockDim.x + threadIdx.x;
    if (i < NN) c1[i] = 0;
    else if (i < 2 * NN) c2[i - NN] = 0;
}

__global__ void count_both_kernel(const int* __restrict__ ei1, int E1,
                                  const int* __restrict__ ei2, int E2,
                                  int* __restrict__ c1, int* __restrict__ c2) {
    int i = blockIdx.x * blockDim.x + threadIdx.x;
    if (i < E1) atomicAdd(&c1[ei1[E1 + i]], 1);
    else if (i < E1 + E2) atomicAdd(&c2[ei2[E2 + (i - E1)]], 1);
}

// Phase A: per-tile partial sums (1024 elements/block) + fused dinv.
__global__ __launch_bounds__(256) void partial_dinv_kernel(
    const int* __restrict__ c1, float* __restrict__ d1, int* __restrict__ p1,
    const int* __restrict__ c2, float* __restrict__ d2, int* __restrict__ p2)
{
    int set = (blockIdx.x >= NPART) ? 1 : 0;
    int b = blockIdx.x - set * NPART;
    const int* c = set ? c2 : c1;
    float* dv    = set ? d2 : d1;
    int* part    = set ? p2 : p1;

    __shared__ int wsum[8];
    int tid = threadIdx.x;
    int base = b * TILE + tid * 4;
    int s = 0;
    #pragma unroll
    for (int k = 0; k < 4; k++) {
        int i = base + k;
        if (i < NN) {
            int v = c[i];
            s += v;
            dv[i] = rsqrtf((float)v + 1.0f);
        }
    }
    #pragma unroll
    for (int off = 16; off > 0; off >>= 1)
        s += __shfl_down_sync(0xFFFFFFFFu, s, off);
    if ((tid & 31) == 0) wsum[tid >> 5] = s;
    __syncthreads();
    if (tid < 8) {
        int t = wsum[tid];
        #pragma unroll
        for (int off = 4; off > 0; off >>= 1)
            t += __shfl_down_sync(0xFFu, t, off);
        if (tid == 0) part[b] = t;
    }
}

// Phase B: exclusive scan of NPART partials per set (2 blocks, 64 threads).
__global__ __launch_bounds__(64) void scan_partials_kernel(
    int* __restrict__ p1, int* __restrict__ rp1,
    int* __restrict__ p2, int* __restrict__ rp2)
{
    int* part = blockIdx.x ? p2 : p1;
    int* rp   = blockIdx.x ? rp2 : rp1;
    __shared__ int w0_total;
    int tid = threadIdx.x;
    int lane = tid & 31;
    int wid = tid >> 5;
    int v = (tid < NPART) ? part[tid] : 0;
    int incl = v;
    #pragma unroll
    for (int off = 1; off < 32; off <<= 1) {
        int t = __shfl_up_sync(0xFFFFFFFFu, incl, off);
        if (lane >= off) incl += t;
    }
    if (tid == 31) w0_total = incl;
    __syncthreads();
    if (wid == 1) incl += w0_total;
    if (tid < NPART) part[tid] = incl - v;       // exclusive offsets
    if (tid == NPART - 1) rp[NN] = incl;         // grand total
}

// Phase C: per-tile scan + offset, writes row_ptr and cursor.
__global__ __launch_bounds__(1024) void scan_tiles_kernel(
    const int* __restrict__ c1, int* __restrict__ rp1, int* __restrict__ cur1,
    const int* __restrict__ p1,
    const int* __restrict__ c2, int* __restrict__ rp2, int* __restrict__ cur2,
    const int* __restrict__ p2)
{
    int set = (blockIdx.x >= NPART) ? 1 : 0;
    int b = blockIdx.x - set * NPART;
    const int* cnt  = set ? c2 : c1;
    int* rp         = set ? rp2 : rp1;
    int* cur        = set ? cur2 : cur1;
    const int* part = set ? p2 : p1;

    __shared__ int warp_sums[32];
    int tid = threadIdx.x;
    int lane = tid & 31;
    int wid = tid >> 5;
    int i = b * TILE + tid;
    int v = (i < NN) ? cnt[i] : 0;
    int incl = v;
    #pragma unroll
    for (int off = 1; off < 32; off <<= 1) {
        int t = __shfl_up_sync(0xFFFFFFFFu, incl, off);
        if (lane >= off) incl += t;
    }
    if (lane == 31) warp_sums[wid] = incl;
    __syncthreads();
    if (wid == 0) {
        int s = warp_sums[lane];
        #pragma unroll
        for (int off = 1; off < 32; off <<= 1) {
            int t = __shfl_up_sync(0xFFFFFFFFu, s, off);
            if (lane >= off) s += t;
        }
        warp_sums[lane] = s;
    }
    __syncthreads();
    int woff = (wid > 0) ? warp_sums[wid - 1] : 0;
    int excl = incl - v + woff + part[b];
    if (i < NN) { rp[i] = excl; cur[i] = excl; }
}

__global__ void fill_both_kernel(const int* __restrict__ ei1, int E1,
                                 int* __restrict__ cur1, int* __restrict__ col1,
                                 const int* __restrict__ ei2, int E2,
                                 int* __restrict__ cur2, int* __restrict__ col2)
{
    int i = blockIdx.x * blockDim.x + threadIdx.x;
    if (i < E1) {
        int s = ei1[i], d = ei1[E1 + i];
        col1[atomicAdd(&cur1[d], 1)] = s;
    } else if (i < E1 + E2) {
        int e = i - E1;
        int s = ei2[e], d = ei2[E2 + e];
        col2[atomicAdd(&cur2[d], 1)] = s;
    }
}

// ---------------------------------------------------------------------------
// GEMM: g[row, col] = (sum_k A[row,k] * W[k,col]) * dinv[row].
// 64x128 block tile, 128 threads, 8x8 outputs per thread (f32x2 packed).
__global__ __launch_bounds__(128) void gemm_scale_kernel(
    const float* __restrict__ A, const float* __restrict__ W,
    const float* __restrict__ dinv, float* __restrict__ g, int nrows)
{
    __shared__ float As[64][132];
    __shared__ float Ws[16][128];

    const int tid = threadIdx.x;
    const int row_base = blockIdx.x * 64;

    #pragma unroll
    for (int i = tid; i < 64 * 32; i += 128) {
        int r = i >> 5, c4 = i & 31;
        float4 v = make_float4(0.f, 0.f, 0.f, 0.f);
        if (row_base + r < nrows)
            v = reinterpret_cast<const float4*>(A)[(long)(row_base + r) * 32 + c4];
        *reinterpret_cast<float4*>(&As[r][c4 * 4]) = v;
    }

    const int tx = tid & 15;
    const int ty = tid >> 4;
    const int col0 = tx * 8;
    const int row0 = ty * 8;

    unsigned long long acc2[8][4];
    #pragma unroll
    for (int r = 0; r < 8; r++)
        #pragma unroll
        for (int c = 0; c < 4; c++) acc2[r][c] = 0ull;

    for (int kc = 0; kc < D; kc += 16) {
        __syncthreads();
        #pragma unroll
        for (int i = tid; i < 512; i += 128) {
            int kk = i >> 5, c4 = i & 31;
            reinterpret_cast<float4*>(&Ws[kk][c4 * 4])[0] =
                reinterpret_cast<const float4*>(W)[(kc + kk) * 32 + c4];
        }
        __syncthreads();

        #pragma unroll
        for (int kk4 = 0; kk4 < 16; kk4 += 4) {
            float4 av[8];
            #pragma unroll
            for (int r = 0; r < 8; r++)
                av[r] = *reinterpret_cast<const float4*>(&As[row0 + r][kc + kk4]);

            #pragma unroll
            for (int j = 0; j < 4; j++) {
                union { float4 f; unsigned long long u[2]; } w0, w1;
                w0.f = *reinterpret_cast<const float4*>(&Ws[kk4 + j][col0]);
                w1.f = *reinterpret_cast<const float4*>(&Ws[kk4 + j][col0 + 4]);
                unsigned long long wv[4] = { w0.u[0], w0.u[1], w1.u[0], w1.u[1] };
                const float* avf = reinterpret_cast<const float*>(av);
                #pragma unroll
                for (int r = 0; r < 8; r++) {
                    unsigned long long aa = pack2(avf[r * 4 + j]);
                    fma2(acc2[r][0], aa, wv[0]);
                    fma2(acc2[r][1], aa, wv[1]);
                    fma2(acc2[r][2], aa, wv[2]);
                    fma2(acc2[r][3], aa, wv[3]);
                }
            }
        }
    }

    #pragma unroll
    for (int r = 0; r < 8; r++) {
        int row = row_base + row0 + r;
        if (row >= nrows) continue;
        unsigned long long dd = pack2(dinv[row]);
        union { float4 f; unsigned long long u[2]; } o0, o1;
        o0.u[0] = mul2(acc2[r][0], dd);
        o0.u[1] = mul2(acc2[r][1], dd);
        o1.u[0] = mul2(acc2[r][2], dd);
        o1.u[1] = mul2(acc2[r][3], dd);
        long base = (long)row * 32 + (col0 >> 2);
        reinterpret_cast<float4*>(g)[base]     = o0.f;
        reinterpret_cast<float4*>(g)[base + 1] = o1.f;
    }
}

// ---------------------------------------------------------------------------
// Gather + finalize: one warp per node, 4-way unrolled for MLP.
__global__ __launch_bounds__(256) void gather_finalize_kernel(
    const float4* __restrict__ g, const int* __restrict__ row_ptr,
    const int* __restrict__ col, const float* __restrict__ dinv,
    const float4* __restrict__ b, float4* __restrict__ out, int relu_mode)
{
    int warp = (blockIdx.x * blockDim.x + threadIdx.x) >> 5;
    int lane = threadIdx.x & 31;
    if (warp >= NN) return;

    long base = (long)warp * 32 + lane;
    float4 a0 = g[base];
    float4 a1 = make_float4(0.f, 0.f, 0.f, 0.f);
    float4 a2 = make_float4(0.f, 0.f, 0.f, 0.f);
    float4 a3 = make_float4(0.f, 0.f, 0.f, 0.f);

    int jb = __ldg(&row_ptr[warp]);
    int je = __ldg(&row_ptr[warp + 1]);
    int j = jb;
    for (; j + 3 < je; j += 4) {
        int s0 = __ldg(&col[j]);
        int s1 = __ldg(&col[j + 1]);
        int s2 = __ldg(&col[j + 2]);
        int s3 = __ldg(&col[j + 3]);
        float4 v0 = g[(long)s0 * 32 + lane];
        float4 v1 = g[(long)s1 * 32 + lane];
        float4 v2 = g[(long)s2 * 32 + lane];
        float4 v3 = g[(long)s3 * 32 + lane];
        a0.x += v0.x; a0.y += v0.y; a0.z += v0.z; a0.w += v0.w;
        a1.x += v1.x; a1.y += v1.y; a1.z += v1.z; a1.w += v1.w;
        a2.x += v2.x; a2.y += v2.y; a2.z += v2.z; a2.w += v2.w;
        a3.x += v3.x; a3.y += v3.y; a3.z += v3.z; a3.w += v3.w;
    }
    for (; j < je; j++) {
        int s = __ldg(&col[j]);
        float4 v = g[(long)s * 32 + lane];
        a0.x += v.x; a0.y += v.y; a0.z += v.z; a0.w += v.w;
    }
    a0.x += a1.x + a2.x + a3.x;
    a0.y += a1.y + a2.y + a3.y;
    a0.z += a1.z + a2.z + a3.z;
    a0.w += a1.w + a2.w + a3.w;

    float dv = dinv[warp];
    float4 bb = b[lane];
    float o[4] = { fmaf(a0.x, dv, bb.x), fmaf(a0.y, dv, bb.y),
                   fmaf(a0.z, dv, bb.z), fmaf(a0.w, dv, bb.w) };
    if (relu_mode) {
        #pragma unroll
        for (int k = 0; k < 4; k++) o[k] = fmaxf(o[k], 0.0f);
    } else {
        #pragma unroll
        for (int k = 0; k < 4; k++) o[k] = (o[k] > 0.0f) ? o[k] : expm1f(o[k]);
    }
    out[base] = make_float4(o[0], o[1], o[2], o[3]);
}

// ---------------------------------------------------------------------------
extern "C" void kernel_launch(void* const* d_in, const int* in_sizes, int n_in,
                              void* d_out, int out_size)
{
    const float* x  = (const float*)d_in[0];
    const float* W1 = (const float*)d_in[1]; const float* b1 = (const float*)d_in[2];
    const float* W2 = (const float*)d_in[3]; const float* b2 = (const float*)d_in[4];
    const float* W3 = (const float*)d_in[5]; const float* b3 = (const float*)d_in[6];
    const float* W4 = (const float*)d_in[7]; const float* b4 = (const float*)d_in[8];
    const int* ei1 = (const int*)d_in[9];
    const int* ei2 = (const int*)d_in[10];
    const int E1 = in_sizes[9] / 2;
    const int E2 = in_sizes[10] / 2;

    float *gp, *actp, *dinv1, *dinv2;
    int *cnt1, *cnt2, *rp1, *rp2, *cur1, *cur2, *col1, *col2, *p1, *p2;
    cudaGetSymbolAddress((void**)&gp,   g_g);
    cudaGetSymbolAddress((void**)&actp, g_act);
    cudaGetSymbolAddress((void**)&dinv1, g_dinv1);
    cudaGetSymbolAddress((void**)&dinv2, g_dinv2);
    cudaGetSymbolAddress((void**)&cnt1, g_cnt1);
    cudaGetSymbolAddress((void**)&cnt2, g_cnt2);
    cudaGetSymbolAddress((void**)&rp1,  g_rowptr1);
    cudaGetSymbolAddress((void**)&rp2,  g_rowptr2);
    cudaGetSymbolAddress((void**)&cur1, g_cursor1);
    cudaGetSymbolAddress((void**)&cur2, g_cursor2);
    cudaGetSymbolAddress((void**)&col1, g_col1);
    cudaGetSymbolAddress((void**)&col2, g_col2);
    cudaGetSymbolAddress((void**)&p1,   g_part1);
    cudaGetSymbolAddress((void**)&p2,   g_part2);

    float* out_z = (float*)d_out;
    float* out_x = (float*)d_out + (long)NN * D;

    // ---- CSR build ----
    zero_both_kernel<<<(2 * NN + 255) / 256, 256>>>(cnt1, cnt2);
    count_both_kernel<<<(E1 + E2 + 255) / 256, 256>>>(ei1, E1, ei2, E2, cnt1, cnt2);
    partial_dinv_kernel<<<2 * NPART, 256>>>(cnt1, dinv1, p1, cnt2, dinv2, p2);
    scan_partials_kernel<<<2, 64>>>(p1, rp1, p2, rp2);
    scan_tiles_kernel<<<2 * NPART, 1024>>>(cnt1, rp1, cur1, p1, cnt2, rp2, cur2, p2);
    fill_both_kernel<<<(E1 + E2 + 255) / 256, 256>>>(ei1, E1, cur1, col1,
                                                     ei2, E2, cur2, col2);

    const int gemm_blocks = (NN + 63) / 64;
    const int gat_blocks  = (NN * 32 + 255) / 256;

    auto layer = [&](const float* A, const float* Wt, const float* bt,
                     const int* rp, const int* col, const float* dinv,
                     float* o, int relu) {
        gemm_scale_kernel<<<gemm_blocks, 128>>>(A, Wt, dinv, gp, NN);
        gather_finalize_kernel<<<gat_blocks, 256>>>(
            (const float4*)gp, rp, col, dinv, (const float4*)bt,
            (float4*)o, relu);
    };

    layer(x,     W1, b1, rp1, col1, dinv1, actp,  0);  // h  = elu(conv1)
    layer(actp,  W2, b2, rp2, col2, dinv2, out_z, 0);  // z  = elu(conv2)
    layer(out_z, W3, b3, rp1, col1, dinv1, actp,  0);  // h  = elu(conv3)
    layer(actp,  W4, b4, rp2, col2, dinv2, out_x, 1);  // xr = relu(conv4)
}